// round 8
// baseline (speedup 1.0000x reference)
#include <cuda_runtime.h>
#include <cuda_fp16.h>

// Problem constants
#define B      8
#define C_IN   16
#define H      128
#define W      128
#define KSIZE  3
#define HO     126
#define WO     126
#define NK     128

#define TILE_X 32
#define TILE_Y 16
#define NTHREADS 512

// Weights fp16, layout [k][t][c]: half index = k*152 + t*16 + c
// per-k stride = 304 B = 19 quads (odd -> random k spreads over 8 bank-quads)
#define WKH     152
#define W_BYTES (NK * WKH * 2)               // 38912

// Data fp16, layout [y][x][c]: record p = ry*34 + rx, half index = p*24 + c
// record = 16 halves (32 B), stride 24 halves = 48 B = 3 quads (odd)
#define DIN_Y   (TILE_Y + KSIZE - 1)         // 18
#define DIN_X   (TILE_X + KSIZE - 1)         // 34
#define DRECH   24
#define D_BYTES (DIN_Y * DIN_X * DRECH * 2)  // 29376
#define D_OFF   W_BYTES

#define SMEM_BYTES (W_BYTES + D_BYTES)       // 68288  (x2 blocks = 136.6 KB/SM)

__global__ __launch_bounds__(NTHREADS, 2)
void kernel_lookup_kernel(const float* __restrict__ data,
                          const int* __restrict__ kernel_idx,
                          const float* __restrict__ weights,
                          float* __restrict__ out)
{
    extern __shared__ __align__(16) char smem[];
    __half* wsm = reinterpret_cast<__half*>(smem);          // [k][t][c]
    __half* dsm = reinterpret_cast<__half*>(smem + D_OFF);  // [p][c]

    const int tid = threadIdx.x;
    const int b   = blockIdx.z;
    const int ty0 = blockIdx.y * TILE_Y;
    const int tx0 = blockIdx.x * TILE_X;

    // Pixel coords; kidx LDG early so it overlaps staging
    const int tx = tid & 31;
    const int ty = tid >> 5;            // 0..15
    const int oy = ty0 + ty;
    const int ox = tx0 + tx;
    const bool valid = (oy < HO) && (ox < WO);

    int k = 0;
    if (valid) k = kernel_idx[((size_t)b * HO + oy) * WO + ox];

    // ---- stage weights: task = (k,c); 9 consecutive floats -> 9 scattered halves ----
    #pragma unroll 1
    for (int p = tid; p < NK * C_IN; p += NTHREADS) {       // 2048 tasks, 4 iters
        int kk = p >> 4;
        int c  = p & 15;
        const float* w = weights + kk * 144 + c * 9;
        #pragma unroll
        for (int t = 0; t < 9; ++t)
            wsm[kk * WKH + t * 16 + c] = __float2half_rn(w[t]);
    }

    // ---- stage data: task = (c, ry); coalesced fp32 row read, scattered half stores ----
    {
        const float* dimg = data + (size_t)b * C_IN * H * W;
        #pragma unroll 1
        for (int task = tid; task < C_IN * DIN_Y; task += NTHREADS) {   // 288 tasks
            int c  = task / DIN_Y;
            int ry = task - c * DIN_Y;
            int gy = ty0 + ry;
            float row[DIN_X];
            if (gy < H) {
                const float4* s4 = reinterpret_cast<const float4*>(dimg + (c * H + gy) * W + tx0);
                #pragma unroll
                for (int j = 0; j < 8; ++j) {
                    float4 v = s4[j];
                    row[j * 4 + 0] = v.x; row[j * 4 + 1] = v.y;
                    row[j * 4 + 2] = v.z; row[j * 4 + 3] = v.w;
                }
                if (tx0 + 33 < W) {
                    const float* s = dimg + (c * H + gy) * W + tx0;
                    row[32] = s[32]; row[33] = s[33];
                } else { row[32] = 0.0f; row[33] = 0.0f; }
            } else {
                #pragma unroll
                for (int j = 0; j < DIN_X; ++j) row[j] = 0.0f;
            }
            __half* drow = dsm + ry * DIN_X * DRECH + c;    // + rx*DRECH
            #pragma unroll
            for (int rx = 0; rx < DIN_X; ++rx)
                drow[rx * DRECH] = __float2half_rn(row[rx]);
        }
    }

    __syncthreads();

    // ---- compute: explicit 2-stage software pipeline over the 9 taps ----
    const uint4* wq    = reinterpret_cast<const uint4*>(smem + k * (WKH * 2));   // 19 quads/k
    const char*  dbase = reinterpret_cast<const char*>(dsm) + (ty * DIN_X + tx) * (DRECH * 2);

    // tap byte offsets into the data tile: (dy*34 + dx) * 48
    const int doff[9] = { 0*48, 1*48, 2*48, 34*48, 35*48, 36*48, 68*48, 69*48, 70*48 };

    float acc0 = 0.f, acc1 = 0.f, acc2 = 0.f, acc3 = 0.f;

    uint4 wA = wq[0], wB = wq[1];
    uint4 dA = reinterpret_cast<const uint4*>(dbase)[0];
    uint4 dB = reinterpret_cast<const uint4*>(dbase)[1];

    #pragma unroll
    for (int t = 0; t < 9; ++t) {
        uint4 wA_n, wB_n, dA_n, dB_n;
        if (t < 8) {
            wA_n = wq[(t + 1) * 2];
            wB_n = wq[(t + 1) * 2 + 1];
            const uint4* dq = reinterpret_cast<const uint4*>(dbase + doff[t + 1]);
            dA_n = dq[0];
            dB_n = dq[1];
        }

        const unsigned* wa = &wA.x;
        const unsigned* da = &dA.x;
        #pragma unroll
        for (int j = 0; j < 4; ++j) {
            float2 wf = __half22float2(*reinterpret_cast<const __half2*>(&wa[j]));
            float2 df = __half22float2(*reinterpret_cast<const __half2*>(&da[j]));
            acc0 = fmaf(wf.x, df.x, acc0);
            acc1 = fmaf(wf.y, df.y, acc1);
        }
        const unsigned* wb = &wB.x;
        const unsigned* db = &dB.x;
        #pragma unroll
        for (int j = 0; j < 4; ++j) {
            float2 wf = __half22float2(*reinterpret_cast<const __half2*>(&wb[j]));
            float2 df = __half22float2(*reinterpret_cast<const __half2*>(&db[j]));
            acc2 = fmaf(wf.x, df.x, acc2);
            acc3 = fmaf(wf.y, df.y, acc3);
        }

        wA = wA_n; wB = wB_n; dA = dA_n; dB = dB_n;
    }

    if (valid)
        out[((size_t)b * HO + oy) * WO + ox] = (acc0 + acc1) + (acc2 + acc3);
}

extern "C" void kernel_launch(void* const* d_in, const int* in_sizes, int n_in,
                              void* d_out, int out_size)
{
    const float* data = (const float*)d_in[0];
    const int*   kidx = (const int*)d_in[1];
    const float* wts  = (const float*)d_in[2];
    float*       outp = (float*)d_out;

    cudaFuncSetAttribute(kernel_lookup_kernel,
                         cudaFuncAttributeMaxDynamicSharedMemorySize,
                         SMEM_BYTES);

    dim3 grid((WO + TILE_X - 1) / TILE_X,      // 4
              (HO + TILE_Y - 1) / TILE_Y,      // 8
              B);                               // 8  -> 256 blocks, 2/SM
    kernel_lookup_kernel<<<grid, NTHREADS, SMEM_BYTES>>>(data, kidx, wts, outp);
}

// round 10
// speedup vs baseline: 1.1130x; 1.1130x over previous
#include <cuda_runtime.h>
#include <cuda_fp16.h>
#include <cstdint>

// Problem constants
#define B      8
#define C_IN   16
#define H      128
#define W      128
#define KSIZE  3
#define HO     126
#define WO     126
#define NK     128

#define TILE   32
#define NTHREADS 1024

// Weight buffer (fp16), final layout shared by gmem staging buffer and smem:
//   main: [k][c][t0..7]  half index = k*136 + c*8 + t   (k-stride 17 uint4, odd)
//   w8  : [c][k]         half index = 17408 + c*128 + k
#define WKH        136
#define W_MAIN_H   (NK * WKH)                // 17408 halves
#define W8_OFF_H   W_MAIN_H
#define W_TOTAL_H  (W_MAIN_H + C_IN * NK)    // 19456 halves
#define W_BYTES    (W_TOTAL_H * 2)           // 38912

// Data tile fp32: [c][34][36]
#define DROWS  (TILE + KSIZE - 1)            // 34
#define DPITCH 36
#define DPLANE (DROWS * DPITCH)              // 1224
#define D_BYTES (C_IN * DPLANE * 4)          // 78336
#define D_OFF   W_BYTES

#define SMEM_BYTES (W_BYTES + D_BYTES)       // 117248

__device__ __align__(16) __half g_wbuf[W_TOTAL_H];

// ---------- cp.async helpers ----------
__device__ __forceinline__ void cp_async16(unsigned int dst, const void* src) {
    asm volatile("cp.async.cg.shared.global [%0], [%1], 16;\n" :: "r"(dst), "l"(src));
}
__device__ __forceinline__ void cp_async8(unsigned int dst, const void* src) {
    asm volatile("cp.async.ca.shared.global [%0], [%1], 8;\n" :: "r"(dst), "l"(src));
}
__device__ __forceinline__ void cp_async_wait_all() {
    asm volatile("cp.async.commit_group;\n");
    asm volatile("cp.async.wait_group 0;\n" ::: "memory");
}

// ---------- kernel 1: one-time weight convert/transpose into g_wbuf ----------
__global__ void prep_weights_kernel(const float* __restrict__ weights)
{
    int i4 = blockIdx.x * blockDim.x + threadIdx.x;
    if (i4 >= (NK * C_IN * 9) / 4) return;               // 4608 float4s
    float4 v = reinterpret_cast<const float4*>(weights)[i4];
    int base = i4 * 4;
    #pragma unroll
    for (int u = 0; u < 4; ++u) {
        int e = base + u;
        int k = e / 144;
        int r = e - k * 144;
        int c = r / 9;
        int t = r - c * 9;
        float f = (u == 0) ? v.x : (u == 1) ? v.y : (u == 2) ? v.z : v.w;
        __half h = __float2half_rn(f);
        if (t < 8) g_wbuf[k * WKH + c * 8 + t] = h;
        else       g_wbuf[W8_OFF_H + c * NK + k] = h;
    }
}

// ---------- kernel 2: main ----------
__global__ __launch_bounds__(NTHREADS, 1)
void kernel_lookup_kernel(const float* __restrict__ data,
                          const int* __restrict__ kernel_idx,
                          float* __restrict__ out)
{
    extern __shared__ __align__(16) char smem[];
    const unsigned int smem_u32 = (unsigned int)__cvta_generic_to_shared(smem);

    const int tid = threadIdx.x;
    const int b   = blockIdx.z;
    const int ty0 = blockIdx.y * TILE;
    const int tx0 = blockIdx.x * TILE;

    // Pixel coords; kidx LDG early so it overlaps staging
    const int tx = tid & 31;
    const int ty = tid >> 5;
    const int oy = ty0 + ty;
    const int ox = tx0 + tx;
    const bool valid = (oy < HO) && (ox < WO);

    int k = 0;
    if (valid) k = kernel_idx[((size_t)b * HO + oy) * WO + ox];

    // ---- stage weights: pure 16B async copy of the prepared buffer ----
    {
        const char* src = reinterpret_cast<const char*>(g_wbuf);
        #pragma unroll 1
        for (int i = tid; i < W_BYTES / 16; i += NTHREADS)       // 2432
            cp_async16(smem_u32 + i * 16, src + i * 16);
    }

    // ---- stage data: per (c,row) 8x16B + optional 8B tail, all async ----
    {
        const float* dimg = data + (size_t)b * C_IN * H * W;
        const bool xtail = (tx0 + 33 < W);
        #pragma unroll 1
        for (int task = tid; task < C_IN * DROWS; task += NTHREADS) {   // 544
            int c  = task / DROWS;
            int ry = task - c * DROWS;
            int gy = ty0 + ry;
            if (gy >= H) continue;      // garbage smem only feeds invalid pixels
            const float* src = dimg + (c * H + gy) * W + tx0;   // 16B aligned
            unsigned int dst = smem_u32 + D_OFF + (c * DPLANE + ry * DPITCH) * 4;
            #pragma unroll
            for (int j = 0; j < 8; ++j)
                cp_async16(dst + j * 16, src + j * 4);
            if (xtail)
                cp_async8(dst + 128, src + 32);
        }
    }

    cp_async_wait_all();
    __syncthreads();

    // ---- compute: 1 px/thread, R6 loop ----
    const uint4*  wk4   = reinterpret_cast<const uint4*>(smem) + k * (WKH / 8);
    const __half* w8k   = reinterpret_cast<const __half*>(smem + W8_OFF_H * 2) + k;
    const float*  dbase = reinterpret_cast<const float*>(smem + D_OFF) + ty * DPITCH + tx;

    float acc0 = 0.f, acc1 = 0.f, acc2 = 0.f;

    #pragma unroll 4
    for (int c = 0; c < C_IN; ++c) {
        uint4 q = wk4[c];
        float2 w01 = __half22float2(*reinterpret_cast<const __half2*>(&q.x));
        float2 w23 = __half22float2(*reinterpret_cast<const __half2*>(&q.y));
        float2 w45 = __half22float2(*reinterpret_cast<const __half2*>(&q.z));
        float2 w67 = __half22float2(*reinterpret_cast<const __half2*>(&q.w));
        float  w8v = __half2float(w8k[c * NK]);
        const float* dp = dbase + c * DPLANE;

        float d00 = dp[0],              d01 = dp[1],              d02 = dp[2];
        float d10 = dp[DPITCH],         d11 = dp[DPITCH + 1],     d12 = dp[DPITCH + 2];
        float d20 = dp[2 * DPITCH],     d21 = dp[2 * DPITCH + 1], d22 = dp[2 * DPITCH + 2];

        acc0 = fmaf(w01.x, d00, acc0);
        acc1 = fmaf(w01.y, d01, acc1);
        acc2 = fmaf(w23.x, d02, acc2);
        acc0 = fmaf(w23.y, d10, acc0);
        acc1 = fmaf(w45.x, d11, acc1);
        acc2 = fmaf(w45.y, d12, acc2);
        acc0 = fmaf(w67.x, d20, acc0);
        acc1 = fmaf(w67.y, d21, acc1);
        acc2 = fmaf(w8v,   d22, acc2);
    }

    if (valid)
        out[((size_t)b * HO + oy) * WO + ox] = acc0 + acc1 + acc2;
}

extern "C" void kernel_launch(void* const* d_in, const int* in_sizes, int n_in,
                              void* d_out, int out_size)
{
    const float* data = (const float*)d_in[0];
    const int*   kidx = (const int*)d_in[1];
    const float* wts  = (const float*)d_in[2];
    float*       outp = (float*)d_out;

    prep_weights_kernel<<<36, 128>>>(wts);   // 4608 threads, one-time convert

    cudaFuncSetAttribute(kernel_lookup_kernel,
                         cudaFuncAttributeMaxDynamicSharedMemorySize,
                         SMEM_BYTES);
    dim3 grid((WO + TILE - 1) / TILE, (HO + TILE - 1) / TILE, B);  // 4 x 4 x 8
    kernel_lookup_kernel<<<grid, NTHREADS, SMEM_BYTES>>>(data, kidx, outp);
}

// round 11
// speedup vs baseline: 1.1849x; 1.0646x over previous
#include <cuda_runtime.h>
#include <cuda_fp16.h>
#include <cstdint>

// Problem constants
#define B      8
#define C_IN   16
#define H      128
#define W      128
#define KSIZE  3
#define HO     126
#define WO     126
#define NK     128

#define TILE   32
#define NTHREADS 1024

// Weights fp16, layout [k][t][c]: half index = k*152 + t*16 + c
// per-k stride 304 B = 19 quads (odd -> random k spreads over 8 bank-quads)
#define WKH     152
#define W_TOTAL_H (NK * WKH)                 // 19456 halves
#define W_BYTES   (W_TOTAL_H * 2)            // 38912

// Data records fp16 in smem: [p][c], p = ry*34+rx, record 32 B, stride 48 B (3 quads)
#define DROWS   (TILE + KSIZE - 1)           // 34
#define NREC    (DROWS * DROWS)              // 1156
#define RECSTR  48
#define D_BYTES (NREC * RECSTR)              // 55488
#define D_OFF   W_BYTES                      // quad-aligned

#define SMEM_BYTES (W_BYTES + D_BYTES)       // 94400

__device__ __align__(16) __half g_wbuf[W_TOTAL_H];
__device__ __align__(16) __half g_dbuf[B * H * W * C_IN];   // [b][h][w][c]

// ---------- cp.async helpers ----------
__device__ __forceinline__ void cp_async16(unsigned int dst, const void* src) {
    asm volatile("cp.async.cg.shared.global [%0], [%1], 16;\n" :: "r"(dst), "l"(src));
}
__device__ __forceinline__ void cp_async_wait_all() {
    asm volatile("cp.async.commit_group;\n");
    asm volatile("cp.async.wait_group 0;\n" ::: "memory");
}

// ---------- prep: weights -> g_wbuf [k][t][c] fp16 ; data -> g_dbuf [b][h][w][c] fp16 ----------
#define WPREP_BLOCKS 36
__global__ void prep_kernel(const float* __restrict__ weights,
                            const float* __restrict__ data)
{
    const int tid = threadIdx.x;                  // 128 threads
    if (blockIdx.x < WPREP_BLOCKS) {
        int i4 = blockIdx.x * 128 + tid;
        if (i4 >= (NK * C_IN * 9) / 4) return;    // 4608 float4s
        float4 v = reinterpret_cast<const float4*>(weights)[i4];
        int base = i4 * 4;
        #pragma unroll
        for (int u = 0; u < 4; ++u) {
            int e = base + u;
            int k = e / 144;
            int r = e - k * 144;
            int c = r / 9;
            int t = r - c * 9;
            float f = (u == 0) ? v.x : (u == 1) ? v.y : (u == 2) ? v.z : v.w;
            g_wbuf[k * WKH + t * 16 + c] = __float2half_rn(f);
        }
    } else {
        // one block per (b, h); thread = w. Reads coalesced per c, writes 32B/thread.
        int idx = blockIdx.x - WPREP_BLOCKS;      // 0..1023
        int b = idx >> 7;
        int h = idx & 127;
        int w = tid;
        const float* src = data + ((size_t)(b * C_IN) * H + h) * W + w;  // + c*H*W
        unsigned hh[8];
        #pragma unroll
        for (int c2 = 0; c2 < 8; ++c2) {
            float f0 = src[(2 * c2 + 0) * H * W];
            float f1 = src[(2 * c2 + 1) * H * W];
            __half2 p = __floats2half2_rn(f0, f1);
            hh[c2] = *reinterpret_cast<unsigned*>(&p);
        }
        uint4* dst = reinterpret_cast<uint4*>(g_dbuf + ((size_t)(b * H + h) * W + w) * C_IN);
        uint4 q0; q0.x = hh[0]; q0.y = hh[1]; q0.z = hh[2]; q0.w = hh[3];
        uint4 q1; q1.x = hh[4]; q1.y = hh[5]; q1.z = hh[6]; q1.w = hh[7];
        dst[0] = q0;
        dst[1] = q1;
    }
}

// ---------- main ----------
__global__ __launch_bounds__(NTHREADS, 1)
void kernel_lookup_kernel(const int* __restrict__ kernel_idx,
                          float* __restrict__ out)
{
    extern __shared__ __align__(16) char smem[];
    const unsigned int smem_u32 = (unsigned int)__cvta_generic_to_shared(smem);

    const int tid = threadIdx.x;
    const int b   = blockIdx.z;
    const int ty0 = blockIdx.y * TILE;
    const int tx0 = blockIdx.x * TILE;

    const int tx = tid & 31;
    const int ty = tid >> 5;
    const int oy = ty0 + ty;
    const int ox = tx0 + tx;
    const bool valid = (oy < HO) && (ox < WO);

    int k = 0;
    if (valid) k = kernel_idx[((size_t)b * HO + oy) * WO + ox];

    // ---- stage weights: coalesced 16B async copies ----
    {
        const char* src = reinterpret_cast<const char*>(g_wbuf);
        #pragma unroll 1
        for (int i = tid; i < W_BYTES / 16; i += NTHREADS)       // 2432
            cp_async16(smem_u32 + i * 16, src + i * 16);
    }

    // ---- stage data records: 32B contiguous gmem -> 48B-strided smem ----
    {
        const __half* dimg = g_dbuf + (size_t)b * H * W * C_IN;
        #pragma unroll 1
        for (int p = tid; p < NREC; p += NTHREADS) {             // 1156 records
            int ry = p / DROWS;
            int rx = p - ry * DROWS;
            int gy = ty0 + ry;
            int gx = tx0 + rx;
            if (gy >= H || gx >= W) continue;   // garbage only feeds invalid px
            const char* src = reinterpret_cast<const char*>(dimg + ((size_t)gy * W + gx) * C_IN);
            unsigned int dst = smem_u32 + D_OFF + p * RECSTR;
            cp_async16(dst,      src);
            cp_async16(dst + 16, src + 16);
        }
    }

    cp_async_wait_all();
    __syncthreads();

    // ---- compute: per tap 2 weight LDS.128 + 2 data LDS.128 ----
    const uint4* wq    = reinterpret_cast<const uint4*>(smem + k * (WKH * 2));   // 19 quads/k
    const char*  dbase = smem + D_OFF + (ty * DROWS + tx) * RECSTR;

    const int doff[9] = { 0*RECSTR, 1*RECSTR, 2*RECSTR,
                          34*RECSTR, 35*RECSTR, 36*RECSTR,
                          68*RECSTR, 69*RECSTR, 70*RECSTR };

    float acc0 = 0.f, acc1 = 0.f, acc2 = 0.f, acc3 = 0.f;

    #pragma unroll
    for (int t = 0; t < 9; ++t) {
        const uint4* dq = reinterpret_cast<const uint4*>(dbase + doff[t]);
        uint4 wA = wq[t * 2];
        uint4 wB = wq[t * 2 + 1];
        uint4 dA = dq[0];
        uint4 dB = dq[1];

        const unsigned* wa = &wA.x;
        const unsigned* da = &dA.x;
        #pragma unroll
        for (int j = 0; j < 4; ++j) {
            float2 wf = __half22float2(*reinterpret_cast<const __half2*>(&wa[j]));
            float2 df = __half22float2(*reinterpret_cast<const __half2*>(&da[j]));
            acc0 = fmaf(wf.x, df.x, acc0);
            acc1 = fmaf(wf.y, df.y, acc1);
        }
        const unsigned* wb = &wB.x;
        const unsigned* db = &dB.x;
        #pragma unroll
        for (int j = 0; j < 4; ++j) {
            float2 wf = __half22float2(*reinterpret_cast<const __half2*>(&wb[j]));
            float2 df = __half22float2(*reinterpret_cast<const __half2*>(&db[j]));
            acc2 = fmaf(wf.x, df.x, acc2);
            acc3 = fmaf(wf.y, df.y, acc3);
        }
    }

    if (valid)
        out[((size_t)b * HO + oy) * WO + ox] = (acc0 + acc1) + (acc2 + acc3);
}

extern "C" void kernel_launch(void* const* d_in, const int* in_sizes, int n_in,
                              void* d_out, int out_size)
{
    const float* data = (const float*)d_in[0];
    const int*   kidx = (const int*)d_in[1];
    const float* wts  = (const float*)d_in[2];
    float*       outp = (float*)d_out;

    prep_kernel<<<WPREP_BLOCKS + B * H, 128>>>(wts, data);   // weights + data transpose

    cudaFuncSetAttribute(kernel_lookup_kernel,
                         cudaFuncAttributeMaxDynamicSharedMemorySize,
                         SMEM_BYTES);
    dim3 grid((WO + TILE - 1) / TILE, (HO + TILE - 1) / TILE, B);  // 4 x 4 x 8
    kernel_lookup_kernel<<<grid, NTHREADS, SMEM_BYTES>>>(kidx, outp);
}